// round 16
// baseline (speedup 1.0000x reference)
#include <cuda_runtime.h>
#include <cuda_bf16.h>
#include <cstdint>
#include <math.h>

// Problem constants (fixed by the reference)
#define BROWS 8192
#define KROWS 8192
#define DIM   1024
#define WCOLS 2048
#define SIGMA 1.0f

// Level-1 screen dims: partial sqdist over the first SD dims is a LOWER BOUND
// on the full sqdist (sum of nonnegative terms) -> sound for arbitrary inputs.
// THRESH=110: the reference can only produce a nonzero score when its fp32
// sqdist < ~104 (+<=1 rounding), so passing requires true partial >= 110 > 106
// -> full > 106 -> score is exactly 0. At SD=128 the chi-square left tail at
// the effective threshold (~118) is ~3e-8/pair -> ~2 expected candidates,
// refined exactly in fp32 by level 2.
#define SD 128

// ---------------------------------------------------------------------------
// Scratch (static device globals — no allocation)
#define CAND_CAP (1u << 20)
__device__ int          g_flag;
__device__ unsigned int g_cnt;
__device__ uint2        g_cand[CAND_CAP];
__device__ float g_xsq[BROWS];               // partial (first SD dims)
__device__ float g_csq[KROWS];               // partial (first SD dims)
__device__ __nv_bfloat16 g_xb[BROWS * SD];
__device__ __nv_bfloat16 g_cb[KROWS * SD];

// ---------------------------------------------------------------------------
// PTX helpers (base sm_103 target only — NO tcgen05, harness compiles compute_103)
__device__ __forceinline__ uint32_t smem_u32(const void* p) {
    uint32_t a;
    asm("{ .reg .u64 t; cvta.to.shared.u64 t, %1; cvt.u32.u64 %0, t; }" : "=r"(a) : "l"(p));
    return a;
}
__device__ __forceinline__ void cp16(uint32_t dst, const void* src) {
    asm volatile("cp.async.cg.shared.global [%0], [%1], 16;\n" :: "r"(dst), "l"(src));
}
__device__ __forceinline__ void cp_commit() {
    asm volatile("cp.async.commit_group;\n" ::: "memory");
}
template <int N>
__device__ __forceinline__ void cp_wait() {
    asm volatile("cp.async.wait_group %0;\n" :: "n"(N) : "memory");
}
__device__ __forceinline__ void ldsm_x4(uint32_t& r0, uint32_t& r1, uint32_t& r2, uint32_t& r3,
                                        uint32_t addr) {
    asm volatile("ldmatrix.sync.aligned.m8n8.x4.shared.b16 {%0,%1,%2,%3}, [%4];"
                 : "=r"(r0), "=r"(r1), "=r"(r2), "=r"(r3) : "r"(addr));
}
__device__ __forceinline__ void mma_bf16(float& c0, float& c1, float& c2, float& c3,
                                         uint32_t a0, uint32_t a1, uint32_t a2, uint32_t a3,
                                         uint32_t b0, uint32_t b1) {
    asm volatile(
        "mma.sync.aligned.m16n8k16.row.col.f32.bf16.bf16.f32 "
        "{%0,%1,%2,%3}, {%4,%5,%6,%7}, {%8,%9}, {%0,%1,%2,%3};"
        : "+f"(c0), "+f"(c1), "+f"(c2), "+f"(c3)
        : "r"(a0), "r"(a1), "r"(a2), "r"(a3), "r"(b0), "r"(b1));
}
#define SWZ128(off) ((off) ^ (((off) >> 3) & 0x70))

// ---------------------------------------------------------------------------
// Fused reset + convert + partial norms over first SD=128 dims.
// 8 rows per 256-thread block; 1 warp per row; 1 float4 per lane per tensor.
__global__ void __launch_bounds__(256)
convert_norms_kernel(const float* __restrict__ x, const float* __restrict__ w) {
    if (blockIdx.x == 0 && threadIdx.x == 0) { g_flag = 0; g_cnt = 0; }

    const int lane = threadIdx.x & 31;
    const int row = blockIdx.x * 8 + (threadIdx.x >> 5);

    float4 vx = *(const float4*)(x + (size_t)row * DIM + lane * 4);
    float4 vw = *(const float4*)(w + (size_t)row * WCOLS + lane * 4);

    {
        __nv_bfloat162* dx = (__nv_bfloat162*)(g_xb + (size_t)row * SD + lane * 4);
        dx[0] = __floats2bfloat162_rn(vx.x, vx.y);
        dx[1] = __floats2bfloat162_rn(vx.z, vx.w);
        __nv_bfloat162* dc = (__nv_bfloat162*)(g_cb + (size_t)row * SD + lane * 4);
        dc[0] = __floats2bfloat162_rn(vw.x, vw.y);
        dc[1] = __floats2bfloat162_rn(vw.z, vw.w);
    }
    float sx = vx.x * vx.x + vx.y * vx.y + vx.z * vx.z + vx.w * vx.w;
    float sc = vw.x * vw.x + vw.y * vw.y + vw.z * vw.z + vw.w * vw.w;
#pragma unroll
    for (int st = 16; st > 0; st >>= 1) {
        sx += __shfl_xor_sync(0xffffffffu, sx, st);
        sc += __shfl_xor_sync(0xffffffffu, sc, st);
    }
    if (lane == 0) { g_xsq[row] = sx; g_csq[row] = sc; }
}

// ---------------------------------------------------------------------------
// Persistent HMMA bf16 screen: 148 CTAs stream ~14 tiles each (2 chunks/tile)
// through a 4-stage cp.async ring (loads 3 chunks ahead, one barrier per
// chunk). 16 warps (512 thr), 2x8 warp grid, 64x32 per warp (proven core).
// Emits candidate pairs for exact refinement instead of a global flag.
#define TM 128
#define TN 256
#define BKC 64
#define CPT 2                      // chunks per tile (SD / BKC)
#define NT_N (KROWS / TN)          // 32
#define NT_M (BROWS / TM)          // 64
#define NTILES (NT_N * NT_M)       // 2048
#define PGRID 148

#define STG_BYTES ((TM + TN) * 128)   // 48 KB
#define NSTG 4
#define SM_TOTAL (NSTG * STG_BYTES)   // 192 KB

// Reference nonzero needs fp32 sqdist < ~104 (+<=1 rounding) -> 110 is a
// sound screen threshold; candidates are refined exactly so false positives
// only cost refine time.
#define CHECK_THRESH 110.0f
#define REFINE_THRESH 130.0f

__device__ __forceinline__ void push_cand(int r, int c) {
    unsigned idx = atomicAdd(&g_cnt, 1u);
    if (idx < CAND_CAP) g_cand[idx] = make_uint2((unsigned)r, (unsigned)c);
    else atomicExch(&g_flag, 1);   // overflow: conservative full fallback
}

__global__ void __launch_bounds__(512, 1)
check_kernel_mma(float* __restrict__ out) {
    extern __shared__ char smem[];
    const uint32_t sb = smem_u32(smem);
    const int tid = threadIdx.x;
    const int lane = tid & 31;
    const int wid = tid >> 5;
    const int wm = wid >> 3;          // 0..1 -> M offset wm*64
    const int wn = wid & 7;           // 0..7 -> N offset wn*32

    const int bx = blockIdx.x;
    const int n_local = (NTILES - bx + PGRID - 1) / PGRID;   // tiles for this CTA
    const int total = n_local * CPT;                          // chunks

    auto issue_load = [&](int k) {
        const int t = bx + (k / CPT) * PGRID;
        const int mb = (t >> 5) * TM;          // t / NT_N
        const int nb = (t & (NT_N - 1)) * TN;  // t % NT_N
        const int c = k - (k / CPT) * CPT;
        const uint32_t ab = sb + (k & (NSTG - 1)) * STG_BYTES;
        const uint32_t bb = ab + TM * 128;
        const __nv_bfloat16* asrc = g_xb + (size_t)mb * SD + c * BKC;
        const __nv_bfloat16* bsrc = g_cb + (size_t)nb * SD + c * BKC;
#pragma unroll
        for (int i = 0; i < 2; i++) {
            int idx = i * 512 + tid;
            int row = idx >> 3, ch = idx & 7;
            cp16(ab + SWZ128(row * 128 + ch * 16), asrc + (size_t)row * SD + ch * 8);
        }
#pragma unroll
        for (int i = 0; i < 4; i++) {
            int idx = i * 512 + tid;
            int row = idx >> 3, ch = idx & 7;
            cp16(bb + SWZ128(row * 128 + ch * 16), bsrc + (size_t)row * SD + ch * 8);
        }
    };

    // prologue: first 3 chunks in flight (total >= 26 always)
    issue_load(0); cp_commit();
    issue_load(1); cp_commit();
    issue_load(2); cp_commit();

    // zero-fill this CTA's strided slice of the 32MB output (fast-path answer),
    // overlapped with loads/MMA — DRAM store path is otherwise idle here.
    {
        float4 z = make_float4(0.f, 0.f, 0.f, 0.f);
        float4* o = (float4*)out;
        for (size_t i = (size_t)bx * 512 + tid; i < (size_t)BROWS * DIM / 4;
             i += (size_t)PGRID * 512)
            o[i] = z;
    }

    float acc[4][4][4];
#pragma unroll
    for (int mi = 0; mi < 4; mi++)
#pragma unroll
        for (int nj = 0; nj < 4; nj++)
#pragma unroll
            for (int f = 0; f < 4; f++) acc[mi][nj][f] = 0.f;

    for (int k = 0; k < total; k++) {
        // chunk k lives in commit-group k; exactly one commit per iteration
        // (empty near the end), so wait_group 2 always means "group k done".
        cp_wait<2>();
        __syncthreads();

        const uint32_t ab = sb + (k & (NSTG - 1)) * STG_BYTES;
        const uint32_t bb = ab + TM * 128;

#pragma unroll
        for (int ks = 0; ks < BKC / 16; ks++) {
            uint32_t bfr[8];
#pragma unroll
            for (int g = 0; g < 2; g++) {
                int n = wn * 32 + g * 16 + (lane & 7) + ((lane & 16) >> 1);
                int ch = ks * 2 + ((lane >> 3) & 1);
                ldsm_x4(bfr[g * 4 + 0], bfr[g * 4 + 1], bfr[g * 4 + 2], bfr[g * 4 + 3],
                        bb + SWZ128(n * 128 + ch * 16));
            }
#pragma unroll
            for (int mi = 0; mi < 4; mi++) {
                int m = wm * 64 + mi * 16 + (lane & 15);
                int ch = ks * 2 + (lane >> 4);
                uint32_t a0, a1, a2, a3;
                ldsm_x4(a0, a1, a2, a3, ab + SWZ128(m * 128 + ch * 16));
#pragma unroll
                for (int nj = 0; nj < 4; nj++) {
                    mma_bf16(acc[mi][nj][0], acc[mi][nj][1], acc[mi][nj][2], acc[mi][nj][3],
                             a0, a1, a2, a3, bfr[nj * 2], bfr[nj * 2 + 1]);
                }
            }
        }

        if ((k & 1) == CPT - 1) {
            // tile epilogue: partial-sqdist screen -> candidate push (bf16
            // slack (xs+cs)/64 conservatively covers dot rounding; NaN pushes
            // via !(>=)), then reset accumulators.
            const int t = bx + (k / CPT) * PGRID;
            const int mbase = (t >> 5) * TM;
            const int nbase = (t & (NT_N - 1)) * TN;
            const int r0 = mbase + wm * 64 + (lane >> 2);
            const int c0 = nbase + wn * 32 + (lane & 3) * 2;
#pragma unroll
            for (int mi = 0; mi < 4; mi++) {
                float xsA = g_xsq[r0 + mi * 16];
                float xsB = g_xsq[r0 + mi * 16 + 8];
#pragma unroll
                for (int nj = 0; nj < 4; nj++) {
                    float cs0 = g_csq[c0 + nj * 8];
                    float cs1 = g_csq[c0 + nj * 8 + 1];
                    float e;
                    e = xsA + cs0 - 2.f * acc[mi][nj][0];
                    if (!(e >= CHECK_THRESH + (xsA + cs0) * 0.015625f))
                        push_cand(r0 + mi * 16, c0 + nj * 8);
                    e = xsA + cs1 - 2.f * acc[mi][nj][1];
                    if (!(e >= CHECK_THRESH + (xsA + cs1) * 0.015625f))
                        push_cand(r0 + mi * 16, c0 + nj * 8 + 1);
                    e = xsB + cs0 - 2.f * acc[mi][nj][2];
                    if (!(e >= CHECK_THRESH + (xsB + cs0) * 0.015625f))
                        push_cand(r0 + mi * 16 + 8, c0 + nj * 8);
                    e = xsB + cs1 - 2.f * acc[mi][nj][3];
                    if (!(e >= CHECK_THRESH + (xsB + cs1) * 0.015625f))
                        push_cand(r0 + mi * 16 + 8, c0 + nj * 8 + 1);
                }
            }
#pragma unroll
            for (int mi = 0; mi < 4; mi++)
#pragma unroll
                for (int nj = 0; nj < 4; nj++)
#pragma unroll
                    for (int f = 0; f < 4; f++) acc[mi][nj][f] = 0.f;
        }

        // issue next load AFTER compute; always commit for uniform counts.
        if (k + 3 < total) issue_load(k + 3);
        cp_commit();
    }
}

// ---------------------------------------------------------------------------
// Level-2 refine: exact fp32 full-DIM sqdist per candidate (one warp each,
// grid-stride). Direct fp32 computation differs from the reference's by <= ~1
// at these magnitudes, so flagging when direct sqdist < 130 is conservative.
__global__ void __launch_bounds__(256)
refine_kernel(const float* __restrict__ x, const float* __restrict__ w) {
    const int lane = threadIdx.x & 31;
    const int warp = (blockIdx.x * blockDim.x + threadIdx.x) >> 5;
    const int nwarps = (gridDim.x * blockDim.x) >> 5;
    const unsigned n = min(g_cnt, CAND_CAP);

    for (unsigned i = warp; i < n; i += nwarps) {
        uint2 p = g_cand[i];
        const float* xr = x + (size_t)p.x * DIM;
        const float* cr = w + (size_t)p.y * WCOLS;
        float s = 0.f;
#pragma unroll
        for (int j = 0; j < DIM / 128; j++) {
            float4 a = *(const float4*)(xr + j * 128 + lane * 4);
            float4 b = *(const float4*)(cr + j * 128 + lane * 4);
            float d0 = a.x - b.x, d1 = a.y - b.y, d2 = a.z - b.z, d3 = a.w - b.w;
            s += d0 * d0 + d1 * d1 + d2 * d2 + d3 * d3;
        }
#pragma unroll
        for (int st = 16; st > 0; st >>= 1) s += __shfl_xor_sync(0xffffffffu, s, st);
        if (lane == 0 && !(s >= REFINE_THRESH)) atomicExch(&g_flag, 1);
    }
}

// ---------------------------------------------------------------------------
// Fixup: output is already zero-filled (the exact fast-path answer — every
// score underflows to 0.0f in the fp32 reference). Only if refine (or
// candidate overflow) flagged does this recompute rows exactly in fp32.
__global__ void __launch_bounds__(256)
fixup_kernel(const float* __restrict__ x, const float* __restrict__ w,
             float* __restrict__ out) {
    if (g_flag == 0) return;

    const int tid = threadIdx.x;
    __shared__ float xs[DIM];
    __shared__ float red[256];
    for (int r = 0; r < 4; r++) {
        const int row = blockIdx.x * 4 + r;
        for (int j = tid; j < DIM; j += 256) xs[j] = x[(size_t)row * DIM + j];
        __syncthreads();

        float acc[4] = {0.f, 0.f, 0.f, 0.f};
        for (int k = 0; k < KROWS; k++) {
            const float* c = w + (size_t)k * WCOLS;
            float p = 0.f;
            for (int j = tid; j < DIM; j += 256) {
                float d = xs[j] - c[j];
                p += d * d;
            }
            red[tid] = p;
            __syncthreads();
            for (int st = 128; st > 0; st >>= 1) {
                if (tid < st) red[tid] += red[tid + st];
                __syncthreads();
            }
            float sq = red[0];
            __syncthreads();
            float s = expf(-SIGMA * sq);
            const float* v = c + DIM;
#pragma unroll
            for (int t = 0; t < 4; t++) acc[t] += s * v[tid + 256 * t];
        }
#pragma unroll
        for (int t = 0; t < 4; t++) out[(size_t)row * DIM + tid + 256 * t] = acc[t];
        __syncthreads();
    }
}

// ---------------------------------------------------------------------------
extern "C" void kernel_launch(void* const* d_in, const int* in_sizes, int n_in,
                              void* d_out, int out_size) {
    const float* x = (const float*)d_in[0];   // [8192, 1024]
    const float* w = (const float*)d_in[1];   // [8192, 2048]
    float* out = (float*)d_out;               // [8192, 1024]

    cudaFuncSetAttribute(check_kernel_mma, cudaFuncAttributeMaxDynamicSharedMemorySize, SM_TOTAL);

    convert_norms_kernel<<<BROWS / 8, 256>>>(x, w);
    check_kernel_mma<<<PGRID, 512, SM_TOTAL>>>(out);
    refine_kernel<<<PGRID, 256>>>(x, w);
    fixup_kernel<<<BROWS / 4, 256>>>(x, w, out);
}

// round 17
// speedup vs baseline: 1.4891x; 1.4891x over previous
#include <cuda_runtime.h>
#include <cuda_bf16.h>
#include <cstdint>
#include <math.h>

// Problem constants (fixed by the reference)
#define BROWS 8192
#define KROWS 8192
#define DIM   1024
#define WCOLS 2048
#define SIGMA 1.0f

// Level-1 screen dims: partial sqdist over the first SD dims is a LOWER BOUND
// on the full sqdist (sum of nonnegative terms) -> sound for arbitrary inputs.
// THRESH=110: reference nonzero needs its fp32 sqdist < ~104 (+<=1 rounding);
// passing the screen proves true partial >= 110 > 106 -> score exactly 0.
// At SD=128 the chi-square left tail at the effective threshold (~118) is
// ~3e-8/pair -> a handful of flagged 64x32 regions, refined exactly.
#define SD 128

// ---------------------------------------------------------------------------
// Scratch (static device globals — no allocation)
#define REG_CAP 16384
__device__ int          g_flag;
__device__ unsigned int g_rcnt;
__device__ uint2        g_reg[REG_CAP];      // (row base, col base) of 64x32 regions
__device__ float g_xsq[BROWS];               // partial (first SD dims)
__device__ float g_csq[KROWS];               // partial (first SD dims)
__device__ __nv_bfloat16 g_xb[BROWS * SD];
__device__ __nv_bfloat16 g_cb[KROWS * SD];

// ---------------------------------------------------------------------------
// PTX helpers (base sm_103 target only — NO tcgen05, harness compiles compute_103)
__device__ __forceinline__ uint32_t smem_u32(const void* p) {
    uint32_t a;
    asm("{ .reg .u64 t; cvta.to.shared.u64 t, %1; cvt.u32.u64 %0, t; }" : "=r"(a) : "l"(p));
    return a;
}
__device__ __forceinline__ void cp16(uint32_t dst, const void* src) {
    asm volatile("cp.async.cg.shared.global [%0], [%1], 16;\n" :: "r"(dst), "l"(src));
}
__device__ __forceinline__ void cp_commit() {
    asm volatile("cp.async.commit_group;\n" ::: "memory");
}
template <int N>
__device__ __forceinline__ void cp_wait() {
    asm volatile("cp.async.wait_group %0;\n" :: "n"(N) : "memory");
}
__device__ __forceinline__ void ldsm_x4(uint32_t& r0, uint32_t& r1, uint32_t& r2, uint32_t& r3,
                                        uint32_t addr) {
    asm volatile("ldmatrix.sync.aligned.m8n8.x4.shared.b16 {%0,%1,%2,%3}, [%4];"
                 : "=r"(r0), "=r"(r1), "=r"(r2), "=r"(r3) : "r"(addr));
}
__device__ __forceinline__ void mma_bf16(float& c0, float& c1, float& c2, float& c3,
                                         uint32_t a0, uint32_t a1, uint32_t a2, uint32_t a3,
                                         uint32_t b0, uint32_t b1) {
    asm volatile(
        "mma.sync.aligned.m16n8k16.row.col.f32.bf16.bf16.f32 "
        "{%0,%1,%2,%3}, {%4,%5,%6,%7}, {%8,%9}, {%0,%1,%2,%3};"
        : "+f"(c0), "+f"(c1), "+f"(c2), "+f"(c3)
        : "r"(a0), "r"(a1), "r"(a2), "r"(a3), "r"(b0), "r"(b1));
}
#define SWZ128(off) ((off) ^ (((off) >> 3) & 0x70))

// ---------------------------------------------------------------------------
// Fused reset + convert + partial norms over first SD=128 dims.
// 8 rows per 256-thread block; 1 warp per row; 1 float4 per lane per tensor.
__global__ void __launch_bounds__(256)
convert_norms_kernel(const float* __restrict__ x, const float* __restrict__ w) {
    if (blockIdx.x == 0 && threadIdx.x == 0) { g_flag = 0; g_rcnt = 0; }

    const int lane = threadIdx.x & 31;
    const int row = blockIdx.x * 8 + (threadIdx.x >> 5);

    float4 vx = *(const float4*)(x + (size_t)row * DIM + lane * 4);
    float4 vw = *(const float4*)(w + (size_t)row * WCOLS + lane * 4);

    {
        __nv_bfloat162* dx = (__nv_bfloat162*)(g_xb + (size_t)row * SD + lane * 4);
        dx[0] = __floats2bfloat162_rn(vx.x, vx.y);
        dx[1] = __floats2bfloat162_rn(vx.z, vx.w);
        __nv_bfloat162* dc = (__nv_bfloat162*)(g_cb + (size_t)row * SD + lane * 4);
        dc[0] = __floats2bfloat162_rn(vw.x, vw.y);
        dc[1] = __floats2bfloat162_rn(vw.z, vw.w);
    }
    float sx = vx.x * vx.x + vx.y * vx.y + vx.z * vx.z + vx.w * vx.w;
    float sc = vw.x * vw.x + vw.y * vw.y + vw.z * vw.z + vw.w * vw.w;
#pragma unroll
    for (int st = 16; st > 0; st >>= 1) {
        sx += __shfl_xor_sync(0xffffffffu, sx, st);
        sc += __shfl_xor_sync(0xffffffffu, sc, st);
    }
    if (lane == 0) { g_xsq[row] = sx; g_csq[row] = sc; }
}

// ---------------------------------------------------------------------------
// Persistent HMMA bf16 screen: 148 CTAs stream ~14 tiles each (2 chunks/tile)
// through a 4-stage cp.async ring (loads 3 chunks ahead, one barrier per
// chunk). 16 warps (512 thr), 2x8 warp grid, 64x32 per warp (proven core).
// Per-tile epilogue mirrors the proven flag shape: __any_sync + ONE lane-0
// push of the warp's 64x32 region for exact refinement.
#define TM 128
#define TN 256
#define BKC 64
#define CPT 2                      // chunks per tile (SD / BKC)
#define NT_N (KROWS / TN)          // 32
#define NT_M (BROWS / TM)          // 64
#define NTILES (NT_N * NT_M)       // 2048
#define PGRID 148

#define STG_BYTES ((TM + TN) * 128)   // 48 KB
#define NSTG 4
#define SM_TOTAL (NSTG * STG_BYTES)   // 192 KB

#define CHECK_THRESH 110.0f
#define REFINE_THRESH 130.0f

__global__ void __launch_bounds__(512, 1)
check_kernel_mma(float* __restrict__ out) {
    extern __shared__ char smem[];
    const uint32_t sb = smem_u32(smem);
    const int tid = threadIdx.x;
    const int lane = tid & 31;
    const int wid = tid >> 5;
    const int wm = wid >> 3;          // 0..1 -> M offset wm*64
    const int wn = wid & 7;           // 0..7 -> N offset wn*32

    const int bx = blockIdx.x;
    const int n_local = (NTILES - bx + PGRID - 1) / PGRID;   // tiles for this CTA
    const int total = n_local * CPT;                          // chunks

    auto issue_load = [&](int k) {
        const int t = bx + (k / CPT) * PGRID;
        const int mb = (t >> 5) * TM;          // t / NT_N
        const int nb = (t & (NT_N - 1)) * TN;  // t % NT_N
        const int c = k - (k / CPT) * CPT;
        const uint32_t ab = sb + (k & (NSTG - 1)) * STG_BYTES;
        const uint32_t bb = ab + TM * 128;
        const __nv_bfloat16* asrc = g_xb + (size_t)mb * SD + c * BKC;
        const __nv_bfloat16* bsrc = g_cb + (size_t)nb * SD + c * BKC;
#pragma unroll
        for (int i = 0; i < 2; i++) {
            int idx = i * 512 + tid;
            int row = idx >> 3, ch = idx & 7;
            cp16(ab + SWZ128(row * 128 + ch * 16), asrc + (size_t)row * SD + ch * 8);
        }
#pragma unroll
        for (int i = 0; i < 4; i++) {
            int idx = i * 512 + tid;
            int row = idx >> 3, ch = idx & 7;
            cp16(bb + SWZ128(row * 128 + ch * 16), bsrc + (size_t)row * SD + ch * 8);
        }
    };

    // prologue: first 3 chunks in flight (total >= 26 always)
    issue_load(0); cp_commit();
    issue_load(1); cp_commit();
    issue_load(2); cp_commit();

    // zero-fill this CTA's strided slice of the 32MB output (fast-path answer),
    // overlapped with loads/MMA — DRAM store path is otherwise idle here.
    {
        float4 z = make_float4(0.f, 0.f, 0.f, 0.f);
        float4* o = (float4*)out;
        for (size_t i = (size_t)bx * 512 + tid; i < (size_t)BROWS * DIM / 4;
             i += (size_t)PGRID * 512)
            o[i] = z;
    }

    float acc[4][4][4];
#pragma unroll
    for (int mi = 0; mi < 4; mi++)
#pragma unroll
        for (int nj = 0; nj < 4; nj++)
#pragma unroll
            for (int f = 0; f < 4; f++) acc[mi][nj][f] = 0.f;

    for (int k = 0; k < total; k++) {
        // chunk k lives in commit-group k; exactly one commit per iteration
        // (empty near the end), so wait_group 2 always means "group k done".
        cp_wait<2>();
        __syncthreads();

        const uint32_t ab = sb + (k & (NSTG - 1)) * STG_BYTES;
        const uint32_t bb = ab + TM * 128;

#pragma unroll
        for (int ks = 0; ks < BKC / 16; ks++) {
            uint32_t bfr[8];
#pragma unroll
            for (int g = 0; g < 2; g++) {
                int n = wn * 32 + g * 16 + (lane & 7) + ((lane & 16) >> 1);
                int ch = ks * 2 + ((lane >> 3) & 1);
                ldsm_x4(bfr[g * 4 + 0], bfr[g * 4 + 1], bfr[g * 4 + 2], bfr[g * 4 + 3],
                        bb + SWZ128(n * 128 + ch * 16));
            }
#pragma unroll
            for (int mi = 0; mi < 4; mi++) {
                int m = wm * 64 + mi * 16 + (lane & 15);
                int ch = ks * 2 + (lane >> 4);
                uint32_t a0, a1, a2, a3;
                ldsm_x4(a0, a1, a2, a3, ab + SWZ128(m * 128 + ch * 16));
#pragma unroll
                for (int nj = 0; nj < 4; nj++) {
                    mma_bf16(acc[mi][nj][0], acc[mi][nj][1], acc[mi][nj][2], acc[mi][nj][3],
                             a0, a1, a2, a3, bfr[nj * 2], bfr[nj * 2 + 1]);
                }
            }
        }

        if ((k & 1) == CPT - 1) {
            // tile epilogue (same shape as the proven flag version): compare,
            // __any_sync, single lane-0 push of this warp's 64x32 region.
            const int t = bx + (k / CPT) * PGRID;
            const int mbase = (t >> 5) * TM;
            const int nbase = (t & (NT_N - 1)) * TN;
            const int r0 = mbase + wm * 64 + (lane >> 2);
            const int c0 = nbase + wn * 32 + (lane & 3) * 2;
            int any = 0;
#pragma unroll
            for (int mi = 0; mi < 4; mi++) {
                float xsA = g_xsq[r0 + mi * 16];
                float xsB = g_xsq[r0 + mi * 16 + 8];
#pragma unroll
                for (int nj = 0; nj < 4; nj++) {
                    float cs0 = g_csq[c0 + nj * 8];
                    float cs1 = g_csq[c0 + nj * 8 + 1];
                    float e;
                    e = xsA + cs0 - 2.f * acc[mi][nj][0];
                    if (!(e >= CHECK_THRESH + (xsA + cs0) * 0.015625f)) any = 1;
                    e = xsA + cs1 - 2.f * acc[mi][nj][1];
                    if (!(e >= CHECK_THRESH + (xsA + cs1) * 0.015625f)) any = 1;
                    e = xsB + cs0 - 2.f * acc[mi][nj][2];
                    if (!(e >= CHECK_THRESH + (xsB + cs0) * 0.015625f)) any = 1;
                    e = xsB + cs1 - 2.f * acc[mi][nj][3];
                    if (!(e >= CHECK_THRESH + (xsB + cs1) * 0.015625f)) any = 1;
                }
            }
            if (__any_sync(0xffffffffu, any)) {
                if (lane == 0) {
                    unsigned idx = atomicAdd(&g_rcnt, 1u);
                    if (idx < REG_CAP)
                        g_reg[idx] = make_uint2((unsigned)(mbase + wm * 64),
                                                (unsigned)(nbase + wn * 32));
                    else
                        atomicExch(&g_flag, 1);
                }
            }
#pragma unroll
            for (int mi = 0; mi < 4; mi++)
#pragma unroll
                for (int nj = 0; nj < 4; nj++)
#pragma unroll
                    for (int f = 0; f < 4; f++) acc[mi][nj][f] = 0.f;
        }

        // issue next load AFTER compute; always commit for uniform counts.
        if (k + 3 < total) issue_load(k + 3);
        cp_commit();
    }
}

// ---------------------------------------------------------------------------
// Level-2 refine: for each flagged 64x32 region, exact fp32 full-DIM sqdist
// for ALL 2048 pairs (one warp per pair, grid-stride). Direct fp32 differs
// from the reference's by <= ~1 here, so flagging when < 130 is conservative.
__global__ void __launch_bounds__(256)
refine_kernel(const float* __restrict__ x, const float* __restrict__ w) {
    const int lane = threadIdx.x & 31;
    const unsigned warp = (blockIdx.x * blockDim.x + threadIdx.x) >> 5;
    const unsigned nwarps = (gridDim.x * blockDim.x) >> 5;
    const unsigned nreg = min(g_rcnt, (unsigned)REG_CAP);
    const unsigned ntasks = nreg * 2048u;

    for (unsigned i = warp; i < ntasks; i += nwarps) {
        uint2 rg = g_reg[i >> 11];
        unsigned pair = i & 2047u;
        const float* xr = x + (size_t)(rg.x + (pair >> 5)) * DIM;
        const float* cr = w + (size_t)(rg.y + (pair & 31u)) * WCOLS;
        float s = 0.f;
#pragma unroll
        for (int j = 0; j < DIM / 128; j++) {
            float4 a = *(const float4*)(xr + j * 128 + lane * 4);
            float4 b = *(const float4*)(cr + j * 128 + lane * 4);
            float d0 = a.x - b.x, d1 = a.y - b.y, d2 = a.z - b.z, d3 = a.w - b.w;
            s += d0 * d0 + d1 * d1 + d2 * d2 + d3 * d3;
        }
#pragma unroll
        for (int st = 16; st > 0; st >>= 1) s += __shfl_xor_sync(0xffffffffu, s, st);
        if (lane == 0 && !(s >= REFINE_THRESH)) atomicExch(&g_flag, 1);
    }
}

// ---------------------------------------------------------------------------
// Fixup: output is already zero-filled (the exact fast-path answer — every
// score underflows to 0.0f in the fp32 reference). Only if refine (or region
// overflow) flagged does this recompute rows exactly in fp32.
__global__ void __launch_bounds__(256)
fixup_kernel(const float* __restrict__ x, const float* __restrict__ w,
             float* __restrict__ out) {
    if (g_flag == 0) return;

    const int tid = threadIdx.x;
    __shared__ float xs[DIM];
    __shared__ float red[256];
    for (int r = 0; r < 4; r++) {
        const int row = blockIdx.x * 4 + r;
        for (int j = tid; j < DIM; j += 256) xs[j] = x[(size_t)row * DIM + j];
        __syncthreads();

        float acc[4] = {0.f, 0.f, 0.f, 0.f};
        for (int k = 0; k < KROWS; k++) {
            const float* c = w + (size_t)k * WCOLS;
            float p = 0.f;
            for (int j = tid; j < DIM; j += 256) {
                float d = xs[j] - c[j];
                p += d * d;
            }
            red[tid] = p;
            __syncthreads();
            for (int st = 128; st > 0; st >>= 1) {
                if (tid < st) red[tid] += red[tid + st];
                __syncthreads();
            }
            float sq = red[0];
            __syncthreads();
            float s = expf(-SIGMA * sq);
            const float* v = c + DIM;
#pragma unroll
            for (int t = 0; t < 4; t++) acc[t] += s * v[tid + 256 * t];
        }
#pragma unroll
        for (int t = 0; t < 4; t++) out[(size_t)row * DIM + tid + 256 * t] = acc[t];
        __syncthreads();
    }
}

// ---------------------------------------------------------------------------
extern "C" void kernel_launch(void* const* d_in, const int* in_sizes, int n_in,
                              void* d_out, int out_size) {
    const float* x = (const float*)d_in[0];   // [8192, 1024]
    const float* w = (const float*)d_in[1];   // [8192, 2048]
    float* out = (float*)d_out;               // [8192, 1024]

    cudaFuncSetAttribute(check_kernel_mma, cudaFuncAttributeMaxDynamicSharedMemorySize, SM_TOTAL);

    convert_norms_kernel<<<BROWS / 8, 256>>>(x, w);
    check_kernel_mma<<<PGRID, 512, SM_TOTAL>>>(out);
    refine_kernel<<<PGRID, 256>>>(x, w);
    fixup_kernel<<<BROWS / 4, 256>>>(x, w, out);
}